// round 1
// baseline (speedup 1.0000x reference)
#include <cuda_runtime.h>
#include <cstdint>
#include <cstddef>

// ---------------------------------------------------------------------------
// InputAttention on GB300 — round 1
//   N=32768 rows, D=1024, HEADS=16, DIM_HEAD=64, L=9 (feat + 8 context rows)
//
// Algebraically reduced pipeline (no K/V materialization):
//   qn = LN_q(feat); cn[l] = LN_c(concat(feat, context))
//   q  = qn @ Wq
//   u[h]  = q[h] @ Wk_h^T                     (batched GEMM, K=64)
//   scores[h,l] = u[h] . cn[l] * 1/8 ; attn = softmax_l
//   w[h]  = sum_l attn[h,l] * cn[l]           (written over u)
//   o[h]  = w[h] @ Wv_h                       (batched GEMM, N=64)
//   out = o @ Wout + bout + feat
//
// All scratch fp32; GEMMs use tf32 mma.sync with fp32 accumulate.
// ---------------------------------------------------------------------------

#define NROWS 32768
#define DDIM  1024

// Scratch (each < 2 GB; u/w split across two arrays by head half)
__device__ float g_qn[(size_t)NROWS * 1024];            // 134 MB
__device__ float g_cn[(size_t)NROWS * 9 * 1024];        // 1.21 GB
__device__ float g_q [(size_t)NROWS * 1024];            // 134 MB
__device__ float g_u0[(size_t)NROWS * 8 * 1024];        // 1.07 GB (heads 0-7, then w)
__device__ float g_u1[(size_t)NROWS * 8 * 1024];        // 1.07 GB (heads 8-15, then w)
__device__ float g_o [(size_t)NROWS * 1024];            // 134 MB

// ---------------------------------------------------------------------------
// LayerNorm kernel: one block per (row, l); l==0 also emits qn.
// ---------------------------------------------------------------------------
__device__ __forceinline__ float block_reduce_sum(float v, float* sh) {
#pragma unroll
    for (int o = 16; o > 0; o >>= 1) v += __shfl_xor_sync(0xffffffffu, v, o);
    int lane = threadIdx.x & 31, w = threadIdx.x >> 5;
    if (lane == 0) sh[w] = v;
    __syncthreads();
    if (threadIdx.x < 8) {
        float t = sh[threadIdx.x];
#pragma unroll
        for (int o = 4; o > 0; o >>= 1) t += __shfl_xor_sync(0xffu, t, o);
        if (threadIdx.x == 0) sh[0] = t;
    }
    __syncthreads();
    float r = sh[0];
    __syncthreads();
    return r;
}

__global__ void __launch_bounds__(256) ln_kernel(
    const float* __restrict__ feat, const float* __restrict__ ctx,
    const float* __restrict__ gq, const float* __restrict__ bq,
    const float* __restrict__ gc, const float* __restrict__ bc)
{
    __shared__ float sh[8];
    int t = blockIdx.x;
    int n = t / 9, l = t - n * 9;
    const float* src = (l == 0) ? feat + (size_t)n * 1024
                                : ctx + ((size_t)n * 8 + (l - 1)) * 1024;
    int tid = threadIdx.x;
    float4 x = ((const float4*)src)[tid];
    float s = block_reduce_sum(x.x + x.y + x.z + x.w, sh);
    float mean = s * (1.0f / 1024.0f);
    float dx = x.x - mean, dy = x.y - mean, dz = x.z - mean, dw = x.w - mean;
    float sq = block_reduce_sum(dx * dx + dy * dy + dz * dz + dw * dw, sh);
    float rs = rsqrtf(sq * (1.0f / 1024.0f) + 1e-5f);

    float4 g = ((const float4*)gc)[tid];
    float4 b = ((const float4*)bc)[tid];
    float4 o;
    o.x = dx * rs * g.x + b.x;  o.y = dy * rs * g.y + b.y;
    o.z = dz * rs * g.z + b.z;  o.w = dw * rs * g.w + b.w;
    ((float4*)(g_cn + ((size_t)n * 9 + l) * 1024))[tid] = o;

    if (l == 0) {
        float4 g2 = ((const float4*)gq)[tid];
        float4 b2 = ((const float4*)bq)[tid];
        float4 o2;
        o2.x = dx * rs * g2.x + b2.x;  o2.y = dy * rs * g2.y + b2.y;
        o2.z = dz * rs * g2.z + b2.z;  o2.w = dw * rs * g2.w + b2.w;
        ((float4*)(g_qn + (size_t)n * 1024))[tid] = o2;
    }
}

// ---------------------------------------------------------------------------
// tf32 tiled GEMM: C[M,N] = A[M,K] @ B[K,N] (+ optional bias/resid epilogue)
//   BCOL: B element (k,n) lives at B[n*ldb + k] (col-major view)
//   batch via blockIdx.z; A/C may be split across two arrays by z<8 / z>=8
//   All tile dims divide problem dims exactly (no bounds checks).
// ---------------------------------------------------------------------------
__device__ __forceinline__ uint32_t f2t(float x) {
    uint32_t u; asm("cvt.rna.tf32.f32 %0, %1;" : "=r"(u) : "f"(x)); return u;
}
__device__ __forceinline__ void mma_tf32(float* c, const uint32_t* a, const uint32_t* b) {
    asm volatile(
        "mma.sync.aligned.m16n8k8.row.col.f32.tf32.tf32.f32 "
        "{%0,%1,%2,%3}, {%4,%5,%6,%7}, {%8,%9}, {%0,%1,%2,%3};"
        : "+f"(c[0]), "+f"(c[1]), "+f"(c[2]), "+f"(c[3])
        : "r"(a[0]), "r"(a[1]), "r"(a[2]), "r"(a[3]), "r"(b[0]), "r"(b[1]));
}

template<int BM, int BN, int BK, bool BCOL, bool EPI>
__global__ void __launch_bounds__(256) gemm_tf32_kernel(
    const float* __restrict__ A0, const float* __restrict__ A1, long aBS, int lda,
    const float* __restrict__ Bg, long bBS, int ldb,
    float* C0, float* C1, long cBS, int ldc,
    int K,
    const float* __restrict__ bias, const float* __restrict__ resid)
{
    constexpr int WM = BM / 4, WN = BN / 2;   // 8 warps: 4 x 2
    constexpr int MF = WM / 16, NF = WN / 8;
    __shared__ uint32_t As[BM][BK + 1];
    __shared__ uint32_t Bs[BK][BN + 4];

    int z = blockIdx.z;
    const float* A = A1 ? ((z < 8 ? A0 : A1) + (size_t)(z & 7) * aBS)
                        : (A0 + (size_t)z * aBS);
    const float* B = Bg + (size_t)z * bBS;
    float* C = C1 ? ((z < 8 ? C0 : C1) + (size_t)(z & 7) * cBS)
                  : (C0 + (size_t)z * cBS);

    int bm = blockIdx.y * BM, bn = blockIdx.x * BN;
    int tid = threadIdx.x, lane = tid & 31, wid = tid >> 5;
    int wm = (wid >> 1) * WM, wn = (wid & 1) * WN;

    float acc[MF][NF][4];
#pragma unroll
    for (int i = 0; i < MF; i++)
#pragma unroll
        for (int j = 0; j < NF; j++)
#pragma unroll
            for (int k = 0; k < 4; k++) acc[i][j][k] = 0.f;

    for (int k0 = 0; k0 < K; k0 += BK) {
        // load A tile (row-major, float4)
#pragma unroll
        for (int it = 0; it < BM * BK / 4 / 256; it++) {
            int i = tid + it * 256;
            int r = i / (BK / 4), kv = i % (BK / 4);
            float4 v = *(const float4*)(A + (size_t)(bm + r) * lda + k0 + kv * 4);
            As[r][kv * 4 + 0] = f2t(v.x); As[r][kv * 4 + 1] = f2t(v.y);
            As[r][kv * 4 + 2] = f2t(v.z); As[r][kv * 4 + 3] = f2t(v.w);
        }
        // load B tile
        if constexpr (BCOL) {
#pragma unroll
            for (int it = 0; it < BK * BN / 256; it++) {
                int i = tid + it * 256;
                int k = i % BK, nn = i / BK;
                Bs[k][nn] = f2t(B[(size_t)(bn + nn) * ldb + k0 + k]);
            }
        } else {
#pragma unroll
            for (int it = 0; it < BK * BN / 4 / 256; it++) {
                int i = tid + it * 256;
                int k = i / (BN / 4), nv = i % (BN / 4);
                float4 v = *(const float4*)(B + (size_t)(k0 + k) * ldb + bn + nv * 4);
                Bs[k][nv * 4 + 0] = f2t(v.x); Bs[k][nv * 4 + 1] = f2t(v.y);
                Bs[k][nv * 4 + 2] = f2t(v.z); Bs[k][nv * 4 + 3] = f2t(v.w);
            }
        }
        __syncthreads();

#pragma unroll
        for (int kk = 0; kk < BK; kk += 8) {
            uint32_t af[MF][4], bf[NF][2];
#pragma unroll
            for (int im = 0; im < MF; im++) {
                int r = wm + im * 16 + (lane >> 2);
                int c = kk + (lane & 3);
                af[im][0] = As[r][c];      af[im][1] = As[r + 8][c];
                af[im][2] = As[r][c + 4];  af[im][3] = As[r + 8][c + 4];
            }
#pragma unroll
            for (int jn = 0; jn < NF; jn++) {
                int col = wn + jn * 8 + (lane >> 2);
                bf[jn][0] = Bs[kk + (lane & 3)][col];
                bf[jn][1] = Bs[kk + 4 + (lane & 3)][col];
            }
#pragma unroll
            for (int im = 0; im < MF; im++)
#pragma unroll
                for (int jn = 0; jn < NF; jn++)
                    mma_tf32(acc[im][jn], af[im], bf[jn]);
        }
        __syncthreads();
    }

    // epilogue
#pragma unroll
    for (int im = 0; im < MF; im++) {
#pragma unroll
        for (int jn = 0; jn < NF; jn++) {
            int r0 = bm + wm + im * 16 + (lane >> 2);
            int c0 = bn + wn + jn * 8 + 2 * (lane & 3);
            float v0 = acc[im][jn][0], v1 = acc[im][jn][1];
            float v2 = acc[im][jn][2], v3 = acc[im][jn][3];
            if constexpr (EPI) {
                v0 += bias[c0]     + resid[(size_t)r0 * ldc + c0];
                v1 += bias[c0 + 1] + resid[(size_t)r0 * ldc + c0 + 1];
                v2 += bias[c0]     + resid[(size_t)(r0 + 8) * ldc + c0];
                v3 += bias[c0 + 1] + resid[(size_t)(r0 + 8) * ldc + c0 + 1];
            }
            C[(size_t)r0 * ldc + c0]           = v0;
            C[(size_t)r0 * ldc + c0 + 1]       = v1;
            C[(size_t)(r0 + 8) * ldc + c0]     = v2;
            C[(size_t)(r0 + 8) * ldc + c0 + 1] = v3;
        }
    }
}

// ---------------------------------------------------------------------------
// Attention core: per row n — scores from u.cn dots, softmax, w = attn.cn,
// w written in place over u.
// ---------------------------------------------------------------------------
__global__ void __launch_bounds__(256) attn_kernel()
{
    __shared__ __align__(16) float cn_s[9 * 1024];   // 36 KB
    __shared__ __align__(16) float u_s[2 * 1024];    // 8 KB (2 heads at a time)
    __shared__ float sc_s[16 * 9];

    int n = blockIdx.x;
    int tid = threadIdx.x, lane = tid & 31, wid = tid >> 5;

    const float4* cn_g = (const float4*)(g_cn + (size_t)n * 9216);
#pragma unroll
    for (int it = 0; it < 9; it++)
        ((float4*)cn_s)[tid + it * 256] = cn_g[tid + it * 256];
    __syncthreads();

    // scores: 16 heads processed 2 at a time
    for (int hg = 0; hg < 8; hg++) {
        const float* ub = (hg < 4 ? g_u0 : g_u1)
                        + (size_t)n * 8192 + (size_t)((2 * hg) & 7) * 1024;
        ((float4*)u_s)[tid]       = ((const float4*)ub)[tid];
        ((float4*)u_s)[tid + 256] = ((const float4*)ub)[tid + 256];
        __syncthreads();

        for (int p = wid; p < 18; p += 8) {
            int hh = p / 9, l = p - hh * 9;
            const float4* u4 = (const float4*)(u_s + hh * 1024);
            const float4* c4 = (const float4*)(cn_s + l * 1024);
            float s = 0.f;
#pragma unroll
            for (int d = 0; d < 8; d++) {
                float4 a = u4[lane + d * 32], b = c4[lane + d * 32];
                s += a.x * b.x + a.y * b.y + a.z * b.z + a.w * b.w;
            }
#pragma unroll
            for (int o = 16; o > 0; o >>= 1) s += __shfl_xor_sync(0xffffffffu, s, o);
            if (lane == 0) sc_s[(2 * hg + hh) * 9 + l] = s;
        }
        __syncthreads();
    }

    // softmax over l (scale 1/sqrt(64) = 0.125)
    if (tid < 16) {
        float m = -1e30f;
#pragma unroll
        for (int l = 0; l < 9; l++) m = fmaxf(m, sc_s[tid * 9 + l]);
        float e[9], sum = 0.f;
#pragma unroll
        for (int l = 0; l < 9; l++) {
            e[l] = expf((sc_s[tid * 9 + l] - m) * 0.125f);
            sum += e[l];
        }
        float inv = 1.0f / sum;
#pragma unroll
        for (int l = 0; l < 9; l++) sc_s[tid * 9 + l] = e[l] * inv;
    }
    __syncthreads();

    // w[h,d] = sum_l attn[h,l] * cn[l,d]  (overwrites u storage)
#pragma unroll 4
    for (int i = 0; i < 64; i++) {
        int idx = i * 256 + tid;
        int h = idx >> 10, d = idx & 1023;
        float a = 0.f;
#pragma unroll
        for (int l = 0; l < 9; l++) a += sc_s[h * 9 + l] * cn_s[l * 1024 + d];
        float* wp = (h < 8 ? g_u0 : g_u1);
        wp[(size_t)n * 8192 + (size_t)(h & 7) * 1024 + d] = a;
    }
}

// ---------------------------------------------------------------------------
// kernel_launch: 6 graph-capturable launches, no allocations.
// ---------------------------------------------------------------------------
extern "C" void kernel_launch(void* const* d_in, const int* in_sizes, int n_in,
                              void* d_out, int out_size)
{
    const float* feat    = (const float*)d_in[0];
    const float* context = (const float*)d_in[1];
    const float* ln_q_g  = (const float*)d_in[2];
    const float* ln_q_b  = (const float*)d_in[3];
    const float* ln_c_g  = (const float*)d_in[4];
    const float* ln_c_b  = (const float*)d_in[5];
    const float* Wq      = (const float*)d_in[6];
    const float* Wk      = (const float*)d_in[7];
    const float* Wv      = (const float*)d_in[8];
    const float* Wout    = (const float*)d_in[9];
    const float* bout    = (const float*)d_in[10];
    float* out = (float*)d_out;

    float *p_qn, *p_cn, *p_q, *p_u0, *p_u1, *p_o;
    cudaGetSymbolAddress((void**)&p_qn, g_qn);
    cudaGetSymbolAddress((void**)&p_cn, g_cn);
    cudaGetSymbolAddress((void**)&p_q,  g_q);
    cudaGetSymbolAddress((void**)&p_u0, g_u0);
    cudaGetSymbolAddress((void**)&p_u1, g_u1);
    cudaGetSymbolAddress((void**)&p_o,  g_o);
    (void)p_cn; (void)in_sizes; (void)n_in; (void)out_size;

    // 1) LayerNorms -> g_qn, g_cn
    ln_kernel<<<NROWS * 9, 256>>>(feat, context, ln_q_g, ln_q_b, ln_c_g, ln_c_b);

    // 2) q = qn @ Wq            [32768,1024] x [1024,1024]
    gemm_tf32_kernel<128, 128, 32, false, false><<<dim3(8, 256, 1), 256>>>(
        p_qn, nullptr, 0, 1024,
        Wq, 0, 1024,
        p_q, nullptr, 0, 1024,
        1024, nullptr, nullptr);

    // 3) u_h = q_h @ Wk_h^T     16 x ([32768,64] x [64,1024]), B col-major view
    gemm_tf32_kernel<128, 128, 32, true, false><<<dim3(8, 256, 16), 256>>>(
        p_q, nullptr, 64, 1024,
        Wk, 64, 1024,
        p_u0, p_u1, 1024, 8192,
        64, nullptr, nullptr);

    // 4) scores -> softmax -> w (in place over u)
    attn_kernel<<<NROWS, 256>>>();

    // 5) o_h = w_h @ Wv_h       16 x ([32768,1024] x [1024,64])
    gemm_tf32_kernel<128, 64, 32, false, false><<<dim3(1, 256, 16), 256>>>(
        p_u0, p_u1, 1024, 8192,
        Wv, 64, 1024,
        p_o, nullptr, 64, 1024,
        1024, nullptr, nullptr);

    // 6) out = o @ Wout + bout + feat
    gemm_tf32_kernel<128, 128, 32, false, true><<<dim3(8, 256, 1), 256>>>(
        p_o, nullptr, 0, 1024,
        Wout, 0, 1024,
        out, nullptr, 0, 1024,
        1024, bout, feat);
}

// round 2
// speedup vs baseline: 3.4428x; 3.4428x over previous
#include <cuda_runtime.h>
#include <cuda_bf16.h>
#include <cstdint>
#include <cstddef>

// ---------------------------------------------------------------------------
// InputAttention on GB300 — round 2: full bf16 pipeline, mma.m16n8k16,
// cp.async double-buffered GEMMs, restructured attention core.
//
//   qn = LN_q(feat); cn[l] = LN_c(concat(feat, context))     (bf16 out)
//   q  = qn @ Wq                                              (bf16 GEMM)
//   u[h]  = q[h] @ Wk_h^T                                     (K=64 GEMM)
//   scores[h,l] = u[h].cn[l] * 0.125 ; attn = softmax_l
//   w[h]  = sum_l attn[h,l] * cn[l]    (in place over u)
//   o[h]  = w[h] @ Wv_h                                       (BN=64 GEMM)
//   out = o @ Wout + bout + feat                              (fp32 out)
// ---------------------------------------------------------------------------

#define NROWS 32768
using bf16 = __nv_bfloat16;

__device__ bf16 g_qn[(size_t)NROWS * 1024];
__device__ bf16 g_cn[(size_t)NROWS * 9 * 1024];
__device__ bf16 g_q [(size_t)NROWS * 1024];
__device__ bf16 g_u [(size_t)NROWS * 16 * 1024];   // u, then w in place
__device__ bf16 g_o [(size_t)NROWS * 1024];
__device__ bf16 g_wq[1024 * 1024];
__device__ bf16 g_wk[1024 * 1024];
__device__ bf16 g_wv[1024 * 1024];
__device__ bf16 g_wo[1024 * 1024];

// ---------------- PTX helpers ----------------
__device__ __forceinline__ uint32_t smem_u32(const void* p) {
    return (uint32_t)__cvta_generic_to_shared(p);
}
__device__ __forceinline__ void cp16(void* s, const void* g) {
    asm volatile("cp.async.cg.shared.global [%0], [%1], 16;"
                 :: "r"(smem_u32(s)), "l"(g));
}
__device__ __forceinline__ void cp_commit() { asm volatile("cp.async.commit_group;"); }
template<int N> __device__ __forceinline__ void cp_wait() {
    asm volatile("cp.async.wait_group %0;" :: "n"(N));
}
__device__ __forceinline__ void ldsm4(uint32_t* r, const void* p) {
    asm volatile("ldmatrix.sync.aligned.m8n8.x4.shared.b16 {%0,%1,%2,%3},[%4];"
        : "=r"(r[0]), "=r"(r[1]), "=r"(r[2]), "=r"(r[3]) : "r"(smem_u32(p)));
}
__device__ __forceinline__ void ldsm4t(uint32_t* r, const void* p) {
    asm volatile("ldmatrix.sync.aligned.m8n8.x4.trans.shared.b16 {%0,%1,%2,%3},[%4];"
        : "=r"(r[0]), "=r"(r[1]), "=r"(r[2]), "=r"(r[3]) : "r"(smem_u32(p)));
}
__device__ __forceinline__ void mma16816(float* c, const uint32_t* a, const uint32_t* b) {
    asm volatile(
        "mma.sync.aligned.m16n8k16.row.col.f32.bf16.bf16.f32 "
        "{%0,%1,%2,%3},{%4,%5,%6,%7},{%8,%9},{%0,%1,%2,%3};"
        : "+f"(c[0]), "+f"(c[1]), "+f"(c[2]), "+f"(c[3])
        : "r"(a[0]), "r"(a[1]), "r"(a[2]), "r"(a[3]), "r"(b[0]), "r"(b[1]));
}
__device__ __forceinline__ uint32_t packbf2(float x, float y) {
    __nv_bfloat162 h = __float22bfloat162_rn(make_float2(x, y));
    return *reinterpret_cast<uint32_t*>(&h);
}

// ---------------- weight convert (fp32 -> bf16) ----------------
__global__ void __launch_bounds__(256) cvt_kernel(
    const float* __restrict__ wq, const float* __restrict__ wk,
    const float* __restrict__ wv, const float* __restrict__ wo)
{
    int i = blockIdx.x * 256 + threadIdx.x;   // 262144 threads, float4 each
    float4 a = ((const float4*)wq)[i];
    ((uint2*)g_wq)[i] = make_uint2(packbf2(a.x, a.y), packbf2(a.z, a.w));
    a = ((const float4*)wk)[i];
    ((uint2*)g_wk)[i] = make_uint2(packbf2(a.x, a.y), packbf2(a.z, a.w));
    a = ((const float4*)wv)[i];
    ((uint2*)g_wv)[i] = make_uint2(packbf2(a.x, a.y), packbf2(a.z, a.w));
    a = ((const float4*)wo)[i];
    ((uint2*)g_wo)[i] = make_uint2(packbf2(a.x, a.y), packbf2(a.z, a.w));
}

// ---------------- LayerNorm ----------------
__device__ __forceinline__ float block_reduce_sum(float v, float* sh) {
#pragma unroll
    for (int o = 16; o > 0; o >>= 1) v += __shfl_xor_sync(0xffffffffu, v, o);
    int lane = threadIdx.x & 31, w = threadIdx.x >> 5;
    if (lane == 0) sh[w] = v;
    __syncthreads();
    if (threadIdx.x < 8) {
        float t = sh[threadIdx.x];
#pragma unroll
        for (int o = 4; o > 0; o >>= 1) t += __shfl_xor_sync(0xffu, t, o);
        if (threadIdx.x == 0) sh[0] = t;
    }
    __syncthreads();
    float r = sh[0];
    __syncthreads();
    return r;
}

__global__ void __launch_bounds__(256) ln_kernel(
    const float* __restrict__ feat, const float* __restrict__ ctx,
    const float* __restrict__ gq, const float* __restrict__ bq,
    const float* __restrict__ gc, const float* __restrict__ bc)
{
    __shared__ float sh[8];
    int t = blockIdx.x;
    int n = t / 9, l = t - n * 9;
    const float* src = (l == 0) ? feat + (size_t)n * 1024
                                : ctx + ((size_t)n * 8 + (l - 1)) * 1024;
    int tid = threadIdx.x;
    float4 x = ((const float4*)src)[tid];
    float s = block_reduce_sum(x.x + x.y + x.z + x.w, sh);
    float mean = s * (1.0f / 1024.0f);
    float dx = x.x - mean, dy = x.y - mean, dz = x.z - mean, dw = x.w - mean;
    float sq = block_reduce_sum(dx * dx + dy * dy + dz * dz + dw * dw, sh);
    float rs = rsqrtf(sq * (1.0f / 1024.0f) + 1e-5f);

    float4 g = ((const float4*)gc)[tid];
    float4 b = ((const float4*)bc)[tid];
    uint2 pk = make_uint2(
        packbf2(dx * rs * g.x + b.x, dy * rs * g.y + b.y),
        packbf2(dz * rs * g.z + b.z, dw * rs * g.w + b.w));
    *reinterpret_cast<uint2*>(g_cn + ((size_t)n * 9 + l) * 1024 + tid * 4) = pk;

    if (l == 0) {
        float4 g2 = ((const float4*)gq)[tid];
        float4 b2 = ((const float4*)bq)[tid];
        uint2 pk2 = make_uint2(
            packbf2(dx * rs * g2.x + b2.x, dy * rs * g2.y + b2.y),
            packbf2(dz * rs * g2.z + b2.z, dw * rs * g2.w + b2.w));
        *reinterpret_cast<uint2*>(g_qn + (size_t)n * 1024 + tid * 4) = pk2;
    }
}

// ---------------------------------------------------------------------------
// Standard bf16 GEMM: C = A @ B (row-major A [M,K], row-major B [K,N]).
// BM=128, BK=32; BN template (128 or 64). cp.async double-buffered, ldmatrix.
// ---------------------------------------------------------------------------
template<int BN, bool EPI, bool CF32>
__global__ void __launch_bounds__(256) gemm_bf16(
    const bf16* __restrict__ A, long aBS, int lda,
    const bf16* __restrict__ B, long bBS, int ldb,
    void* __restrict__ Cv, long cBS, int ldc,
    int K, const float* __restrict__ bias, const float* __restrict__ resid)
{
    constexpr int BM = 128, BK = 32;
    constexpr int AP = BK + 8;           // 40 halves = 80B rows
    constexpr int BP = BN + 8;
    constexpr int NF = BN / 16;          // per-warp n8 tiles (WN = BN/2)
    __shared__ bf16 As[2][BM * AP];
    __shared__ bf16 Bs[2][BK * BP];

    int z = blockIdx.z;
    A += (size_t)z * aBS;
    B += (size_t)z * bBS;

    int bm = blockIdx.y * BM, bn = blockIdx.x * BN;
    int tid = threadIdx.x, lane = tid & 31, wid = tid >> 5;
    int wm = (wid >> 1) * 32, wn = (wid & 1) * (BN / 2);

    float acc[2][NF][4];
#pragma unroll
    for (int i = 0; i < 2; i++)
#pragma unroll
        for (int j = 0; j < NF; j++)
#pragma unroll
            for (int k = 0; k < 4; k++) acc[i][j][k] = 0.f;

    auto loadA = [&](int buf, int k0) {
#pragma unroll
        for (int it = 0; it < 2; it++) {           // 512 chunks / 256 thr
            int i = tid + it * 256;
            int r = i >> 2, kc = i & 3;
            cp16(&As[buf][r * AP + kc * 8],
                 A + (size_t)(bm + r) * lda + k0 + kc * 8);
        }
    };
    auto loadB = [&](int buf, int k0) {
        constexpr int CH = BK * BN / 8;
#pragma unroll
        for (int it = 0; it < CH / 256; it++) {
            int i = tid + it * 256;
            int r = i / (BN / 8), nc = i % (BN / 8);
            cp16(&Bs[buf][r * BP + nc * 8],
                 B + (size_t)(k0 + r) * ldb + bn + nc * 8);
        }
    };
    auto compute = [&](int buf) {
#pragma unroll
        for (int kk = 0; kk < BK; kk += 16) {
            uint32_t af[2][4];
#pragma unroll
            for (int mf = 0; mf < 2; mf++) {
                int r = wm + mf * 16 + ((lane >> 3) & 1) * 8 + (lane & 7);
                int c = kk + (lane >> 4) * 8;
                ldsm4(af[mf], &As[buf][r * AP + c]);
            }
            uint32_t bfr[NF][2];
#pragma unroll
            for (int n2 = 0; n2 < NF / 2; n2++) {
                int kr = kk + ((lane >> 3) & 1) * 8 + (lane & 7);
                int nc = wn + n2 * 16 + (lane >> 4) * 8;
                uint32_t t[4];
                ldsm4t(t, &Bs[buf][kr * BP + nc]);
                bfr[2 * n2][0] = t[0];     bfr[2 * n2][1] = t[1];
                bfr[2 * n2 + 1][0] = t[2]; bfr[2 * n2 + 1][1] = t[3];
            }
#pragma unroll
            for (int mf = 0; mf < 2; mf++)
#pragma unroll
                for (int nf = 0; nf < NF; nf++)
                    mma16816(acc[mf][nf], af[mf], bfr[nf]);
        }
    };

    loadA(0, 0); loadB(0, 0); cp_commit();
    int nIter = K / BK;
    for (int it = 0; it < nIter; it++) {
        if (it + 1 < nIter) {
            loadA((it + 1) & 1, (it + 1) * BK);
            loadB((it + 1) & 1, (it + 1) * BK);
            cp_commit();
            cp_wait<1>();
        } else {
            cp_wait<0>();
        }
        __syncthreads();
        compute(it & 1);
        __syncthreads();
    }

#pragma unroll
    for (int mf = 0; mf < 2; mf++) {
#pragma unroll
        for (int nf = 0; nf < NF; nf++) {
            int r = bm + wm + mf * 16 + (lane >> 2);
            int c = bn + wn + nf * 8 + (lane & 3) * 2;
            float v0 = acc[mf][nf][0], v1 = acc[mf][nf][1];
            float v2 = acc[mf][nf][2], v3 = acc[mf][nf][3];
            if constexpr (CF32) {
                float* C = (float*)Cv + (size_t)z * cBS;
                if constexpr (EPI) {
                    v0 += bias[c]     + resid[(size_t)r * ldc + c];
                    v1 += bias[c + 1] + resid[(size_t)r * ldc + c + 1];
                    v2 += bias[c]     + resid[(size_t)(r + 8) * ldc + c];
                    v3 += bias[c + 1] + resid[(size_t)(r + 8) * ldc + c + 1];
                }
                *(float2*)&C[(size_t)r * ldc + c]       = make_float2(v0, v1);
                *(float2*)&C[(size_t)(r + 8) * ldc + c] = make_float2(v2, v3);
            } else {
                bf16* C = (bf16*)Cv + (size_t)z * cBS;
                *(uint32_t*)&C[(size_t)r * ldc + c]       = packbf2(v0, v1);
                *(uint32_t*)&C[(size_t)(r + 8) * ldc + c] = packbf2(v2, v3);
            }
        }
    }
}

// ---------------------------------------------------------------------------
// gemm_qk: u[n, z, d] = q[n, z*64:+64] @ Wk[d, z*64:+64]^T   (K=64, resident)
// A fragments + B fragments via conflict-free LDS.32 (n-major B smem).
// ---------------------------------------------------------------------------
__global__ void __launch_bounds__(256) gemm_qk_kernel()
{
    constexpr int P = 72;                // 64 + 8 pad halves = 144B rows
    __shared__ bf16 As[128 * P];
    __shared__ bf16 Bs[128 * P];
    int z = blockIdx.z;
    int bm = blockIdx.y * 128, bn = blockIdx.x * 128;
    int tid = threadIdx.x, lane = tid & 31, wid = tid >> 5;
    int wm = (wid >> 1) * 32, wn = (wid & 1) * 64;

#pragma unroll
    for (int it = 0; it < 4; it++) {     // 1024 chunks each of A and B
        int i = tid + it * 256;
        int r = i >> 3, kc = i & 7;
        cp16(&As[r * P + kc * 8],
             g_q + (size_t)(bm + r) * 1024 + z * 64 + kc * 8);
        cp16(&Bs[r * P + kc * 8],
             g_wk + (size_t)(bn + r) * 1024 + z * 64 + kc * 8);
    }
    cp_commit(); cp_wait<0>();
    __syncthreads();

    float acc[2][8][4];
#pragma unroll
    for (int i = 0; i < 2; i++)
#pragma unroll
        for (int j = 0; j < 8; j++)
#pragma unroll
            for (int k = 0; k < 4; k++) acc[i][j][k] = 0.f;

#pragma unroll
    for (int kk = 0; kk < 64; kk += 16) {
        int cc = kk + (lane & 3) * 2;
        uint32_t af[2][4];
#pragma unroll
        for (int mf = 0; mf < 2; mf++) {
            int r = wm + mf * 16 + (lane >> 2);
            af[mf][0] = *(const uint32_t*)&As[r * P + cc];
            af[mf][1] = *(const uint32_t*)&As[(r + 8) * P + cc];
            af[mf][2] = *(const uint32_t*)&As[r * P + cc + 8];
            af[mf][3] = *(const uint32_t*)&As[(r + 8) * P + cc + 8];
        }
        uint32_t bfr[8][2];
#pragma unroll
        for (int nf = 0; nf < 8; nf++) {
            int n = wn + nf * 8 + (lane >> 2);
            bfr[nf][0] = *(const uint32_t*)&Bs[n * P + cc];
            bfr[nf][1] = *(const uint32_t*)&Bs[n * P + cc + 8];
        }
#pragma unroll
        for (int mf = 0; mf < 2; mf++)
#pragma unroll
            for (int nf = 0; nf < 8; nf++)
                mma16816(acc[mf][nf], af[mf], bfr[nf]);
    }

#pragma unroll
    for (int mf = 0; mf < 2; mf++) {
#pragma unroll
        for (int nf = 0; nf < 8; nf++) {
            int r = bm + wm + mf * 16 + (lane >> 2);
            int c = bn + wn + nf * 8 + (lane & 3) * 2;
            bf16* C = g_u + (size_t)r * 16384 + z * 1024;
            *(uint32_t*)&C[c] = packbf2(acc[mf][nf][0], acc[mf][nf][1]);
            *(uint32_t*)&C[(size_t)8 * 16384 + c]
                = packbf2(acc[mf][nf][2], acc[mf][nf][3]);
        }
    }
}

// ---------------------------------------------------------------------------
// attention core: cn resident (18KB), u in two 8-head halves (16KB).
// scores -> softmax -> w (in place over u).
// ---------------------------------------------------------------------------
__global__ void __launch_bounds__(256) attn_kernel()
{
    __shared__ bf16 cn_s[9 * 1024];     // 18KB
    __shared__ bf16 u_s[8 * 1024];      // 16KB
    __shared__ float att[72];
    int n = blockIdx.x, tid = threadIdx.x, lane = tid & 31, wid = tid >> 5;

    {
        const uint2* s = (const uint2*)(g_cn + (size_t)n * 9216);
        uint2* d = (uint2*)cn_s;
#pragma unroll
        for (int it = 0; it < 9; it++) d[tid + it * 256] = s[tid + it * 256];
    }

    for (int hg = 0; hg < 2; hg++) {
        {
            const uint2* s = (const uint2*)(g_u + (size_t)n * 16384 + hg * 8192);
            uint2* d = (uint2*)u_s;
#pragma unroll
            for (int it = 0; it < 8; it++) d[tid + it * 256] = s[tid + it * 256];
        }
        __syncthreads();

        // 72 dot products of length 1024
        for (int p = wid; p < 72; p += 8) {
            int h = p / 9, l = p - h * 9;
            const uint32_t* uu = (const uint32_t*)(u_s + h * 1024);
            const uint32_t* cc = (const uint32_t*)(cn_s + l * 1024);
            float a0 = 0.f, a1 = 0.f;
#pragma unroll
            for (int i = 0; i < 16; i++) {
                float2 av = __bfloat1622float2(
                    *(const __nv_bfloat162*)&uu[i * 32 + lane]);
                float2 bv = __bfloat1622float2(
                    *(const __nv_bfloat162*)&cc[i * 32 + lane]);
                a0 = fmaf(av.x, bv.x, a0);
                a1 = fmaf(av.y, bv.y, a1);
            }
            float s = a0 + a1;
#pragma unroll
            for (int o = 16; o > 0; o >>= 1) s += __shfl_xor_sync(0xffffffffu, s, o);
            if (lane == 0) att[p] = s;
        }
        __syncthreads();

        if (tid < 8) {
            float m = -1e30f;
#pragma unroll
            for (int l = 0; l < 9; l++) m = fmaxf(m, att[tid * 9 + l]);
            float e[9], sum = 0.f;
#pragma unroll
            for (int l = 0; l < 9; l++) {
                e[l] = __expf((att[tid * 9 + l] - m) * 0.125f);
                sum += e[l];
            }
            float inv = 1.0f / sum;
#pragma unroll
            for (int l = 0; l < 9; l++) att[tid * 9 + l] = e[l] * inv;
        }
        __syncthreads();

        // w[h,d] = sum_l attn[h,l]*cn[l,d]  -> overwrite u storage
        bf16* ug = g_u + (size_t)n * 16384 + hg * 8192;
        const uint32_t* cp = (const uint32_t*)cn_s;
#pragma unroll
        for (int i = 0; i < 16; i++) {
            int idx = i * 256 + tid;           // 0..4095 (pairs)
            int h = idx >> 9, dp = idx & 511;
            float sx = 0.f, sy = 0.f;
#pragma unroll
            for (int l = 0; l < 9; l++) {
                float2 c = __bfloat1622float2(
                    *(const __nv_bfloat162*)&cp[l * 512 + dp]);
                float a = att[h * 9 + l];
                sx = fmaf(a, c.x, sx);
                sy = fmaf(a, c.y, sy);
            }
            *(uint32_t*)(ug + h * 1024 + dp * 2) = packbf2(sx, sy);
        }
        __syncthreads();
    }
}

// ---------------------------------------------------------------------------
extern "C" void kernel_launch(void* const* d_in, const int* in_sizes, int n_in,
                              void* d_out, int out_size)
{
    const float* feat    = (const float*)d_in[0];
    const float* context = (const float*)d_in[1];
    const float* ln_q_g  = (const float*)d_in[2];
    const float* ln_q_b  = (const float*)d_in[3];
    const float* ln_c_g  = (const float*)d_in[4];
    const float* ln_c_b  = (const float*)d_in[5];
    const float* Wq      = (const float*)d_in[6];
    const float* Wk      = (const float*)d_in[7];
    const float* Wv      = (const float*)d_in[8];
    const float* Wout    = (const float*)d_in[9];
    const float* bout    = (const float*)d_in[10];
    float* out = (float*)d_out;
    (void)in_sizes; (void)n_in; (void)out_size;

    bf16 *p_qn, *p_q, *p_u, *p_o, *p_wq, *p_wv, *p_wo;
    cudaGetSymbolAddress((void**)&p_qn, g_qn);
    cudaGetSymbolAddress((void**)&p_q,  g_q);
    cudaGetSymbolAddress((void**)&p_u,  g_u);
    cudaGetSymbolAddress((void**)&p_o,  g_o);
    cudaGetSymbolAddress((void**)&p_wq, g_wq);
    cudaGetSymbolAddress((void**)&p_wv, g_wv);
    cudaGetSymbolAddress((void**)&p_wo, g_wo);

    // 0) weights fp32 -> bf16
    cvt_kernel<<<1024, 256>>>(Wq, Wk, Wv, Wout);

    // 1) LayerNorms -> g_qn, g_cn (bf16)
    ln_kernel<<<NROWS * 9, 256>>>(feat, context, ln_q_g, ln_q_b, ln_c_g, ln_c_b);

    // 2) q = qn @ Wq
    gemm_bf16<128, false, false><<<dim3(8, 256, 1), 256>>>(
        p_qn, 0, 1024, p_wq, 0, 1024, p_q, 0, 1024, 1024, nullptr, nullptr);

    // 3) u_h = q_h @ Wk_h^T  (K=64, 16 heads)
    gemm_qk_kernel<<<dim3(8, 256, 16), 256>>>();

    // 4) scores -> softmax -> w (in place over u)
    attn_kernel<<<NROWS, 256>>>();

    // 5) o_h = w_h @ Wv_h   (BN=64, 16 heads)
    gemm_bf16<64, false, false><<<dim3(1, 256, 16), 256>>>(
        p_u, 1024, 16384, p_wv, 64, 1024, p_o, 64, 1024, 1024, nullptr, nullptr);

    // 6) out = o @ Wout + bout + feat  (fp32)
    gemm_bf16<128, true, true><<<dim3(8, 256, 1), 256>>>(
        p_o, 0, 1024, p_wo, 0, 1024, out, 0, 1024, 1024, bout, feat);
}